// round 3
// baseline (speedup 1.0000x reference)
#include <cuda_runtime.h>
#include <math.h>
#include <stdint.h>

// Problem constants (fixed by the dataset)
#define BATCH   16
#define NQ      2048
#define MK      2048
#define DH      128
#define DV      128

// Tiling
#define BM      64        // query rows per CTA
#define BN      64        // key cols per block
#define NTHREADS 128

// Padded smem strides (floats) — chosen so LDS.128 across 8 lanes hits 32 distinct banks
#define QSTR    132
#define KSTR    132
#define VSTR    132
#define PSTR    68

#define SCALE   0.08838834764831843f   // 1/sqrt(128)

__global__ __launch_bounds__(NTHREADS, 2)
void fa_fp32_kernel(const float* __restrict__ q,
                    const float* __restrict__ k,
                    const float* __restrict__ v,
                    const int*   __restrict__ pad,
                    float*       __restrict__ out)
{
    extern __shared__ float sm[];
    float* sQ  = sm;                       // BM * QSTR
    float* sKP = sm + BM * QSTR;           // BN * KSTR  (K tile; reused as P with stride PSTR)
    float* sV  = sKP + BN * KSTR;          // BN * VSTR

    const int tid  = threadIdx.x;
    const int bIdx = blockIdx.x;
    const int b    = bIdx % BATCH;
    // heavy tiles (large causal range) scheduled first to balance waves
    const int tile = (NQ / BM - 1) - (bIdx / BATCH);

    const int keylen = MK - pad[b];        // keys j >= keylen are zeroed -> score 0.0

    const int g  = tid >> 3;               // row group 0..15
    const int c8 = tid & 7;                // col lane 0..7
    const int r0 = g * 4;                  // this thread owns rows r0..r0+3

    // ---- load Q tile (coalesced float4, swizzle-free padded smem) ----
    const float* qbase = q + ((size_t)b * NQ + (size_t)tile * BM) * DH;
    #pragma unroll
    for (int it = 0; it < (BM * DH / 4) / NTHREADS; ++it) {
        int idx = tid + it * NTHREADS;     // float4 index
        int row = idx >> 5;                // DH/4 = 32 float4 per row
        int c4  = idx & 31;
        float4 val = *(const float4*)(qbase + (size_t)row * DH + c4 * 4);
        *(float4*)(sQ + row * QSTR + c4 * 4) = val;
    }

    // ---- per-row online-softmax state + output accumulator ----
    float m_i[4], l_i[4];
    float o[4][16];
    #pragma unroll
    for (int ii = 0; ii < 4; ++ii) {
        m_i[ii] = -1e30f;
        l_i[ii] = 0.0f;
        #pragma unroll
        for (int c = 0; c < 16; ++c) o[ii][c] = 0.0f;
    }

    const int nkb = tile + 1;              // causal: only key blocks with j <= i_max
    const float* kbase = k + (size_t)b * MK * DH;
    const float* vbase = v + (size_t)b * MK * DV;

    for (int kb = 0; kb < nkb; ++kb) {
        __syncthreads();   // Q visible (iter 0) / previous P,V reads complete

        // ---- load K and V blocks ----
        #pragma unroll
        for (int it = 0; it < (BN * DH / 4) / NTHREADS; ++it) {
            int idx = tid + it * NTHREADS;
            int row = idx >> 5;
            int c4  = idx & 31;
            size_t grow = (size_t)(kb * BN + row);
            *(float4*)(sKP + row * KSTR + c4 * 4) =
                *(const float4*)(kbase + grow * DH + c4 * 4);
            *(float4*)(sV + row * VSTR + c4 * 4) =
                *(const float4*)(vbase + grow * DV + c4 * 4);
        }
        __syncthreads();

        // ---- S = Q * K^T : 4x8 microtile per thread ----
        float acc[4][8];
        #pragma unroll
        for (int ii = 0; ii < 4; ++ii)
            #pragma unroll
            for (int jj = 0; jj < 8; ++jj) acc[ii][jj] = 0.0f;

        #pragma unroll 4
        for (int d4 = 0; d4 < DH / 4; ++d4) {
            float4 qf[4];
            #pragma unroll
            for (int ii = 0; ii < 4; ++ii)
                qf[ii] = *(const float4*)(sQ + (r0 + ii) * QSTR + d4 * 4);
            #pragma unroll
            for (int jj = 0; jj < 8; ++jj) {
                float4 kf = *(const float4*)(sKP + (c8 + 8 * jj) * KSTR + d4 * 4);
                #pragma unroll
                for (int ii = 0; ii < 4; ++ii) {
                    acc[ii][jj] = fmaf(qf[ii].x, kf.x, acc[ii][jj]);
                    acc[ii][jj] = fmaf(qf[ii].y, kf.y, acc[ii][jj]);
                    acc[ii][jj] = fmaf(qf[ii].z, kf.z, acc[ii][jj]);
                    acc[ii][jj] = fmaf(qf[ii].w, kf.w, acc[ii][jj]);
                }
            }
        }

        __syncthreads();   // all K reads done; sKP can be overwritten with P

        // ---- masking + online softmax (registers + shfl within 8-lane row group) ----
        #pragma unroll
        for (int ii = 0; ii < 4; ++ii) {
            const int irow = tile * BM + r0 + ii;
            float rm = -1e30f;
            float s[8];
            #pragma unroll
            for (int jj = 0; jj < 8; ++jj) {
                const int jcol = kb * BN + c8 + 8 * jj;
                float sv = acc[ii][jj] * SCALE;
                if (jcol >= keylen) sv = 0.0f;     // zeroed key -> exact 0 score
                if (jcol > irow)    sv = -1e30f;   // causal mask -> exp underflows to 0
                s[jj] = sv;
                rm = fmaxf(rm, sv);
            }
            rm = fmaxf(rm, __shfl_xor_sync(0xffffffffu, rm, 1));
            rm = fmaxf(rm, __shfl_xor_sync(0xffffffffu, rm, 2));
            rm = fmaxf(rm, __shfl_xor_sync(0xffffffffu, rm, 4));
            const float mnew = fmaxf(m_i[ii], rm);

            float rs = 0.0f;
            #pragma unroll
            for (int jj = 0; jj < 8; ++jj) {
                float e = __expf(s[jj] - mnew);
                s[jj] = e;
                rs += e;
            }
            rs += __shfl_xor_sync(0xffffffffu, rs, 1);
            rs += __shfl_xor_sync(0xffffffffu, rs, 2);
            rs += __shfl_xor_sync(0xffffffffu, rs, 4);

            const float alpha = __expf(m_i[ii] - mnew);
            m_i[ii] = mnew;
            l_i[ii] = l_i[ii] * alpha + rs;
            #pragma unroll
            for (int c = 0; c < 16; ++c) o[ii][c] *= alpha;

            // write P into the (retired) K buffer
            #pragma unroll
            for (int jj = 0; jj < 8; ++jj)
                sKP[(r0 + ii) * PSTR + c8 + 8 * jj] = s[jj];
        }
        __syncthreads();

        // ---- O += P * V : 4x16 microtile per thread ----
        #pragma unroll 4
        for (int j0 = 0; j0 < BN; j0 += 4) {
            float pr[4][4];
            #pragma unroll
            for (int ii = 0; ii < 4; ++ii)
                *reinterpret_cast<float4*>(pr[ii]) =
                    *(const float4*)(sKP + (r0 + ii) * PSTR + j0);
            #pragma unroll
            for (int jj = 0; jj < 4; ++jj) {
                float4 vv[4];
                #pragma unroll
                for (int kk = 0; kk < 4; ++kk)
                    vv[kk] = *(const float4*)(sV + (j0 + jj) * VSTR + c8 * 4 + 32 * kk);
                #pragma unroll
                for (int ii = 0; ii < 4; ++ii) {
                    const float pij = pr[ii][jj];
                    #pragma unroll
                    for (int kk = 0; kk < 4; ++kk) {
                        o[ii][kk * 4 + 0] = fmaf(pij, vv[kk].x, o[ii][kk * 4 + 0]);
                        o[ii][kk * 4 + 1] = fmaf(pij, vv[kk].y, o[ii][kk * 4 + 1]);
                        o[ii][kk * 4 + 2] = fmaf(pij, vv[kk].z, o[ii][kk * 4 + 2]);
                        o[ii][kk * 4 + 3] = fmaf(pij, vv[kk].w, o[ii][kk * 4 + 3]);
                    }
                }
            }
        }
    }

    // ---- epilogue: normalize and store (coalesced float4) ----
    float* obase = out + ((size_t)b * NQ + (size_t)tile * BM) * DV;
    #pragma unroll
    for (int ii = 0; ii < 4; ++ii) {
        const float inv = 1.0f / l_i[ii];
        #pragma unroll
        for (int kk = 0; kk < 4; ++kk) {
            float4 val;
            val.x = o[ii][kk * 4 + 0] * inv;
            val.y = o[ii][kk * 4 + 1] * inv;
            val.z = o[ii][kk * 4 + 2] * inv;
            val.w = o[ii][kk * 4 + 3] * inv;
            *(float4*)(obase + (size_t)(r0 + ii) * DV + c8 * 4 + 32 * kk) = val;
        }
    }
}

extern "C" void kernel_launch(void* const* d_in, const int* in_sizes, int n_in,
                              void* d_out, int out_size)
{
    const float* q   = (const float*)d_in[0];
    const float* k   = (const float*)d_in[1];
    const float* v   = (const float*)d_in[2];
    const int*   pad = (const int*)d_in[3];
    float* out = (float*)d_out;

    const size_t smem = (size_t)(BM * QSTR + BN * KSTR + BN * VSTR) * sizeof(float);
    cudaFuncSetAttribute(fa_fp32_kernel,
                         cudaFuncAttributeMaxDynamicSharedMemorySize, (int)smem);

    dim3 grid((NQ / BM) * BATCH);   // 512 CTAs
    fa_fp32_kernel<<<grid, NTHREADS, smem>>>(q, k, v, pad, out);
}